// round 7
// baseline (speedup 1.0000x reference)
#include <cuda_runtime.h>
#include <cuda_bf16.h>
#include <cstdint>

// Embedding_78666620994160
// out[t, e] = (W[e, ids[t]] + b[e]) * sqrt(512)
// ids: [8*4096] int32, W: [512, 50257] f32 (row-major), b: [512] f32
// out: [8*4096, 512] f32
//
// v6: ONE persistent kernel: hist -> grid bar -> scan -> grid bar ->
// scatter -> grid bar -> strided gather loop. 592 blocks = 148 SMs x occ4
// (hw max for 512-thr blocks), epoch-monotonic barriers (graph-replay safe).

#define VOCAB    50257
#define EMB      512
#define N_TOKENS (8 * 4096)
#define BUCKET_SHIFT 5
#define NBINS_PAD 2048

#define NBLK 592
#define NTHR 512
#define TOK_PER_BLK 32
#define E4_PER_BLK  64
#define S4_PITCH    65
#define NTILES ((N_TOKENS / TOK_PER_BLK) * 2)   // 2048

__device__ int  g_hist[NBINS_PAD];     // zeroed at load; scan re-zeroes
__device__ int  g_offs[NBINS_PAD];
__device__ int2 g_sorted[N_TOKENS];

// monotonic barrier counters (never reset; epoch-relative)
__device__ volatile int g_bar0 = 0;
__device__ volatile int g_bar1 = 0;
__device__ volatile int g_bar2 = 0;
__device__ int g_epoch = 0;

__device__ __forceinline__ void grid_bar(volatile int* ctr, int e0)
{
    __threadfence();                 // make this thread's writes L2-visible
    __syncthreads();                 // whole block done with phase
    if (threadIdx.x == 0) {
        atomicAdd((int*)ctr, 1);
        const int target = e0 * NBLK + NBLK;
        while (*ctr < target) __nanosleep(32);
    }
    __syncthreads();
    __threadfence();                 // acquire
}

__global__ void __launch_bounds__(NTHR, 4)
emb_fused_kernel(const int* __restrict__ ids,
                 const float* __restrict__ W,
                 const float* __restrict__ b,
                 float* __restrict__ out)
{
    const float SCALE = 22.62741699796952f; // sqrt(512)
    __shared__ float4 S4[TOK_PER_BLK * S4_PITCH];
    __shared__ int    wsum[16];

    const int tid  = threadIdx.x;
    const int e0   = g_epoch;                    // stable across launch
    const int gtid = blockIdx.x * NTHR + tid;

    // ---- Phase A: histogram (blocks 0..63) ----
    int id = 0;
    if (gtid < N_TOKENS) {
        id = __ldg(&ids[gtid]);
        atomicAdd(&g_hist[id >> BUCKET_SHIFT], 1);
    }
    grid_bar(&g_bar0, e0);

    // ---- Phase B: block 0 scans 2048 bins (4/thread), zeroes hist ----
    if (blockIdx.x == 0) {
        int lane = tid & 31, wid = tid >> 5;
        int base = tid * 4;
        int v0 = g_hist[base + 0], v1 = g_hist[base + 1];
        int v2 = g_hist[base + 2], v3 = g_hist[base + 3];
        g_hist[base + 0] = 0; g_hist[base + 1] = 0;
        g_hist[base + 2] = 0; g_hist[base + 3] = 0;
        int s = v0 + v1 + v2 + v3;

        int x = s;
        #pragma unroll
        for (int off = 1; off < 32; off <<= 1) {
            int y = __shfl_up_sync(0xffffffffu, x, off);
            if (lane >= off) x += y;
        }
        if (lane == 31) wsum[wid] = x;
        __syncthreads();
        if (wid == 0 && lane < 16) {
            int w = wsum[lane];
            int xw = w;
            #pragma unroll
            for (int off = 1; off < 16; off <<= 1) {
                int y = __shfl_up_sync(0x0000ffffu, xw, off);
                if (lane >= off) xw += y;
            }
            wsum[lane] = xw - w;                 // exclusive warp base
        }
        __syncthreads();

        int run = wsum[wid] + (x - s);
        g_offs[base + 0] = run;            run += v0;
        g_offs[base + 1] = run;            run += v1;
        g_offs[base + 2] = run;            run += v2;
        g_offs[base + 3] = run;
        __syncthreads();                         // wsum reuse safety
    }
    grid_bar(&g_bar1, e0);

    // ---- Phase C: scatter ----
    if (gtid < N_TOKENS) {
        int pos = atomicAdd(&g_offs[id >> BUCKET_SHIFT], 1);
        __stcs(&g_sorted[pos], make_int2(gtid, id));
    }
    grid_bar(&g_bar2, e0);

    if (blockIdx.x == 0 && tid == 0) g_epoch = e0 + 1;  // for next replay

    // ---- Phase D: persistent transposed gather ----
    const int t  = tid & 31;                     // local token lane
    const int ty = tid >> 5;                     // 0..15
    const int tl = tid >> 4;                     // 0..31 (phase 2)
    const int ey = tid & 15;                     // 0..15 (phase 2)

    for (int tile = blockIdx.x; tile < NTILES; tile += NBLK) {
        int tg = tile >> 1;                      // token group (32 tokens)
        int e4base = (tile & 1) * E4_PER_BLK;    // emb half

        int sid = __ldg(&g_sorted[tg * TOK_PER_BLK + t]).y;

        #pragma unroll
        for (int i = 0; i < 4; i++) {
            int e4l = ty + 16 * i;
            int e4g = e4base + e4l;
            float4 bv = __ldg((const float4*)b + e4g);
            const float* wp = W + (size_t)(4 * e4g) * VOCAB + sid;
            float4 r;
            r.x = (__ldg(wp)                     + bv.x) * SCALE;
            r.y = (__ldg(wp + (size_t)VOCAB)     + bv.y) * SCALE;
            r.z = (__ldg(wp + (size_t)2 * VOCAB) + bv.z) * SCALE;
            r.w = (__ldg(wp + (size_t)3 * VOCAB) + bv.w) * SCALE;
            S4[t * S4_PITCH + e4l] = r;
        }
        __syncthreads();

        int token = __ldg(&g_sorted[tg * TOK_PER_BLK + tl]).x;
        float4* outp = (float4*)out + (size_t)token * (EMB / 4) + e4base;
        #pragma unroll
        for (int i = 0; i < 4; i++) {
            int e4l = ey + 16 * i;
            __stcs(&outp[e4l], S4[tl * S4_PITCH + e4l]);
        }
        __syncthreads();                         // S4 reuse next tile
    }
}

extern "C" void kernel_launch(void* const* d_in, const int* in_sizes, int n_in,
                              void* d_out, int out_size)
{
    const int*   ids = (const int*)d_in[0];    // [32768] int32
    const float* W   = (const float*)d_in[1];  // [512*50257]
    const float* b   = (const float*)d_in[2];  // [512]
    float*       out = (float*)d_out;          // [32768*512]

    emb_fused_kernel<<<NBLK, NTHR>>>(ids, W, b, out);
}